// round 1
// baseline (speedup 1.0000x reference)
#include <cuda_runtime.h>

#define T_LEN 2048
#define NB 8
#define HD 512
#define VO 5000
#define NT (T_LEN * NB)                 // 16384
#define Y_ELEMS (NB * T_LEN * VO)       // 81,920,000

typedef unsigned long long ull;

// ---------------- device scratch (static: no allocation allowed) ----------------
__device__ float g_Hall[NT * HD];       // 32 MB: h_t for all (t, n)
__device__ float g_h[2][NB * HD];       // ping-pong hidden state
__device__ unsigned g_cnt[NB * 32];     // per-batch barrier counters (padded)
__device__ volatile unsigned g_flag[NB * 32];

// ---------------- packed f32x2 helpers ----------------
__device__ __forceinline__ ull pack2(float x, float y) {
    ull r; asm("mov.b64 %0, {%1, %2};" : "=l"(r) : "f"(x), "f"(y)); return r;
}
__device__ __forceinline__ float2 unpack2(ull a) {
    float2 f; asm("mov.b64 {%0, %1}, %2;" : "=f"(f.x), "=f"(f.y) : "l"(a)); return f;
}
__device__ __forceinline__ void fma2(ull& d, ull a, ull b) {
    asm("fma.rn.f32x2 %0, %1, %2, %0;" : "+l"(d) : "l"(a), "l"(b));
}

// ---------------- init: reset h0 and barrier state every run ----------------
__global__ void init_kernel() {
    int i = threadIdx.x;
    for (int j = i; j < NB * HD; j += blockDim.x) g_h[0][j] = 0.0f;
    if (i < NB * 32) { g_cnt[i] = 0; *(unsigned*)&g_flag[i] = 0; }
}

// ---------------- phase 1: recurrence ----------------
// 128 CTAs = 8 batch-groups x 16 feature-groups, 256 threads.
// CTA (n, fg) owns features [fg*32, fg*32+32) of batch row n.
// Wh slice lives in registers (32 ull = 64 f32 per thread).
__global__ __launch_bounds__(256) void rnn_kernel(const int* __restrict__ x,
                                                  const float* __restrict__ E,
                                                  const float* __restrict__ Wh,
                                                  const float* __restrict__ bh) {
    __shared__ float hs[HD];
    __shared__ int tok_s;
    const int tid = threadIdx.x;
    const int n   = blockIdx.x >> 4;
    const int fg  = blockIdx.x & 15;
    const int jj  = tid >> 3;      // 0..31  feature within slice
    const int sub = tid & 7;       // 0..7   k-partition
    const int jg  = fg * 32 + jj;  // global feature

    // preload Wh row slice into registers: k pairs p = i*8+sub (conflict-free LDS pattern later)
    ull w[32];
    {
        const float2* wr = (const float2*)(Wh + (size_t)jg * HD);
#pragma unroll
        for (int i = 0; i < 32; i++) { float2 f = __ldg(&wr[i * 8 + sub]); w[i] = pack2(f.x, f.y); }
    }
    float bias = (sub == 0) ? __ldg(&bh[jg]) : 0.0f;
    const ull* h2 = (const ull*)hs;

    for (int t = 0; t < T_LEN; t++) {
        const int cur = t & 1, nxt = cur ^ 1;
        __syncthreads();  // protects hs reuse + covers barrier release from prev iter
        if (tid < 128) {
            const float4* s = (const float4*)&g_h[cur][n * HD];
            ((float4*)hs)[tid] = __ldcg(&s[tid]);
        }
        if (tid == 248) tok_s = __ldg(&x[n * T_LEN + t]);
        __syncthreads();

        float eb = 0.0f;
        if (sub == 0) eb = __ldg(&E[(size_t)tok_s * HD + jg]) + bias;  // overlaps with dot

        ull a0 = 0, a1 = 0, a2 = 0, a3 = 0;
#pragma unroll
        for (int i = 0; i < 32; i += 4) {
            fma2(a0, w[i + 0], h2[(i + 0) * 8 + sub]);
            fma2(a1, w[i + 1], h2[(i + 1) * 8 + sub]);
            fma2(a2, w[i + 2], h2[(i + 2) * 8 + sub]);
            fma2(a3, w[i + 3], h2[(i + 3) * 8 + sub]);
        }
        float2 f0 = unpack2(a0), f1 = unpack2(a1), f2 = unpack2(a2), f3 = unpack2(a3);
        float s = (f0.x + f0.y) + (f1.x + f1.y) + (f2.x + f2.y) + (f3.x + f3.y);
        s += __shfl_down_sync(0xffffffffu, s, 4);
        s += __shfl_down_sync(0xffffffffu, s, 2);
        s += __shfl_down_sync(0xffffffffu, s, 1);
        if (sub == 0) {
            float hv = tanhf(s + eb);
            __stcg(&g_h[nxt][n * HD + jg], hv);          // L2-visible for peer CTAs
            g_Hall[((size_t)((t << 3) | n)) * HD + jg] = hv;
            __threadfence();
        }
        __syncthreads();
        if (tid == 0) {  // per-batch epoch barrier among 16 CTAs
            unsigned target = (unsigned)(t + 1);
            unsigned v = atomicAdd(&g_cnt[n * 32], 1u);
            if ((v & 15u) == 15u) {
                atomicExch((unsigned*)&g_flag[n * 32], target);
            } else {
                while (g_flag[n * 32] < target) { }
            }
            __threadfence();
        }
    }
}

// ---------------- phase 2: z = H_all @ Wo^T + bo  (writes raw logits to out) ----------------
// 128x64x32 tile, 256 threads, 8x4 outputs/thread, k-pair packed f32x2 smem layout.
__global__ __launch_bounds__(256, 2) void gemm_kernel(const float* __restrict__ Wo,
                                                      const float* __restrict__ bo,
                                                      float* __restrict__ out) {
    __shared__ ull Asp[16 * 130];   // [kk2][m] padded
    __shared__ ull Bsp[16 * 66];    // [kk2][v] padded
    const int tid = threadIdx.x;
    const int bn = blockIdx.x, bm = blockIdx.y;
    const int m0 = tid & 15;             // rows m0 + 16*i  (interleaved: conflict-free frags)
    const int n0 = (tid >> 4) << 2;      // cols n0..n0+3

    ull acc[8][4];
#pragma unroll
    for (int i = 0; i < 8; i++)
#pragma unroll
        for (int j = 0; j < 4; j++) acc[i][j] = 0;

    const float* Ab = g_Hall + (size_t)bm * 128 * HD;

    for (int k0 = 0; k0 < HD; k0 += 32) {
#pragma unroll
        for (int j = 0; j < 4; j++) {                 // A tile: 128x32
            int lin = tid + j * 256;
            int m = lin >> 3, kq = lin & 7;
            float4 v = *(const float4*)(Ab + (size_t)m * HD + k0 + (kq << 2));
            Asp[(kq * 2 + 0) * 130 + m] = pack2(v.x, v.y);
            Asp[(kq * 2 + 1) * 130 + m] = pack2(v.z, v.w);
        }
#pragma unroll
        for (int j = 0; j < 2; j++) {                 // B tile: 64x32 (guarded at V edge)
            int lin = tid + j * 256;
            int vl = lin >> 3, kq = lin & 7;
            int col = bn * 64 + vl;
            float4 v = make_float4(0.f, 0.f, 0.f, 0.f);
            if (col < VO) v = *(const float4*)(Wo + (size_t)col * HD + k0 + (kq << 2));
            Bsp[(kq * 2 + 0) * 66 + vl] = pack2(v.x, v.y);
            Bsp[(kq * 2 + 1) * 66 + vl] = pack2(v.z, v.w);
        }
        __syncthreads();
#pragma unroll
        for (int kk2 = 0; kk2 < 16; kk2++) {
            ull a[8], b[4];
#pragma unroll
            for (int i = 0; i < 8; i++) a[i] = Asp[kk2 * 130 + m0 + (i << 4)];
#pragma unroll
            for (int j = 0; j < 4; j++) b[j] = Bsp[kk2 * 66 + n0 + j];
#pragma unroll
            for (int i = 0; i < 8; i++)
#pragma unroll
                for (int j = 0; j < 4; j++) fma2(acc[i][j], a[i], b[j]);
        }
        __syncthreads();
    }

    float bov[4];
#pragma unroll
    for (int j = 0; j < 4; j++) {
        int col = bn * 64 + n0 + j;
        bov[j] = (col < VO) ? __ldg(&bo[col]) : 0.0f;
    }
#pragma unroll
    for (int i = 0; i < 8; i++) {
        int rr = bm * 128 + m0 + (i << 4);
        int tt = rr >> 3, n = rr & 7;
        float* orow = out + (size_t)(n * T_LEN + tt) * VO;
#pragma unroll
        for (int j = 0; j < 4; j++) {
            int col = bn * 64 + n0 + j;
            if (col < VO) {
                float2 f = unpack2(acc[i][j]);
                orow[col] = f.x + f.y + bov[j];
            }
        }
    }
}

// ---------------- phase 3: in-place row softmax (row held in registers) ----------------
__global__ __launch_bounds__(256) void softmax_kernel(float* __restrict__ out) {
    const int row = blockIdx.x;
    float* p = out + (size_t)row * VO;
    const int tid = threadIdx.x;
    __shared__ float red[8];

    float v[20];
    float mx = -3.0e38f;
#pragma unroll
    for (int s = 0; s < 20; s++) {
        int i = tid + (s << 8);
        v[s] = (i < VO) ? p[i] : -3.0e38f;
        mx = fmaxf(mx, v[s]);
    }
#pragma unroll
    for (int o = 16; o; o >>= 1) mx = fmaxf(mx, __shfl_xor_sync(0xffffffffu, mx, o));
    if ((tid & 31) == 0) red[tid >> 5] = mx;
    __syncthreads();
    if (tid == 0) {
        float m = red[0];
#pragma unroll
        for (int w = 1; w < 8; w++) m = fmaxf(m, red[w]);
        red[0] = m;
    }
    __syncthreads();
    mx = red[0];

    float sum = 0.0f;
#pragma unroll
    for (int s = 0; s < 20; s++) {
        float e = __expf(v[s] - mx);   // invalid slots: exp(-inf) = 0
        v[s] = e;
        sum += e;
    }
#pragma unroll
    for (int o = 16; o; o >>= 1) sum += __shfl_xor_sync(0xffffffffu, sum, o);
    __syncthreads();                   // everyone done reading red[0] as max
    if ((tid & 31) == 0) red[tid >> 5] = sum;
    __syncthreads();
    if (tid == 0) {
        float s2 = 0.0f;
#pragma unroll
        for (int w = 0; w < 8; w++) s2 += red[w];
        red[0] = s2;
    }
    __syncthreads();
    float r = 1.0f / red[0];
#pragma unroll
    for (int s = 0; s < 20; s++) {
        int i = tid + (s << 8);
        if (i < VO) p[i] = v[s] * r;
    }
}

// ---------------- h_final tail (final state lives in g_h[0]: T even) ----------------
__global__ void copyh_kernel(float* __restrict__ out) {
    int i = blockIdx.x * 256 + threadIdx.x;
    if (i < NB * HD) out[(size_t)Y_ELEMS + i] = g_h[0][i];
}

extern "C" void kernel_launch(void* const* d_in, const int* in_sizes, int n_in,
                              void* d_out, int out_size) {
    const int*   x  = (const int*)d_in[0];
    const float* E  = (const float*)d_in[1];
    const float* Wh = (const float*)d_in[2];
    const float* bh = (const float*)d_in[3];
    const float* Wo = (const float*)d_in[4];
    const float* bo = (const float*)d_in[5];
    float* out = (float*)d_out;

    init_kernel<<<1, 512>>>();
    rnn_kernel<<<128, 256>>>(x, E, Wh, bh);
    dim3 g((VO + 63) / 64, NT / 128);
    gemm_kernel<<<g, 256>>>(Wo, bo, out);
    softmax_kernel<<<NT, 256>>>(out);
    if (out_size >= Y_ELEMS + NB * HD) copyh_kernel<<<16, 256>>>(out);
}

// round 2
// speedup vs baseline: 1.5954x; 1.5954x over previous
#include <cuda_runtime.h>

#define T_LEN 2048
#define NB 8
#define HD 512
#define VO 5000
#define NT (T_LEN * NB)                 // 16384
#define Y_ELEMS (NB * T_LEN * VO)       // 81,920,000

typedef unsigned long long ull;

// ---------------- device scratch (static: no allocation allowed) ----------------
__device__ float g_Hall[NT * HD];       // 32 MB: h_t for all (t, n), row = t*8+n
__device__ float g_hfin[NB * HD];       // final hidden state

// ---------------- packed f32x2 helpers ----------------
__device__ __forceinline__ ull pack2(float x, float y) {
    ull r; asm("mov.b64 %0, {%1, %2};" : "=l"(r) : "f"(x), "f"(y)); return r;
}
__device__ __forceinline__ float2 unpack2(ull a) {
    float2 f; asm("mov.b64 {%0, %1}, %2;" : "=f"(f.x), "=f"(f.y) : "l"(a)); return f;
}
__device__ __forceinline__ void fma2(ull& d, ull a, ull b) {
    asm("fma.rn.f32x2 %0, %1, %2, %0;" : "+l"(d) : "l"(a), "l"(b));
}
__device__ __forceinline__ unsigned smem_u32(const void* p) {
    unsigned a;
    asm("{ .reg .u64 t; cvta.to.shared.u64 t, %1; cvt.u32.u64 %0, t; }" : "=r"(a) : "l"(p));
    return a;
}
__device__ __forceinline__ void st_cluster_f32(unsigned local_addr, unsigned rank, float v) {
    unsigned ra;
    asm("mapa.shared::cluster.u32 %0, %1, %2;" : "=r"(ra) : "r"(local_addr), "r"(rank));
    asm volatile("st.shared::cluster.f32 [%0], %1;" :: "r"(ra), "f"(v) : "memory");
}
#define CLUSTER_SYNC() do { \
    asm volatile("barrier.cluster.arrive.aligned;" ::: "memory"); \
    asm volatile("barrier.cluster.wait.aligned;"   ::: "memory"); \
} while (0)

// ---------------- phase 1: recurrence via CGA (8 CTAs per batch row) ----------------
// Cluster c = batch row n. CTA rank r owns features [r*64, r*64+64).
// 256 threads: feature f = tid>>2 (64), sub = tid&3 (k-partition of 128 floats each).
// k mapping per (q, sub): 16B chunk index (q*4+sub), q = 0..31  -> conflict-free,
// 8-way-broadcast LDS.128 of the shared h vector.
__global__ __cluster_dims__(8, 1, 1) __launch_bounds__(256)
void rnn_kernel(const int* __restrict__ x,
                const float* __restrict__ E,
                const float* __restrict__ Wh,
                const float* __restrict__ bh) {
    __shared__ __align__(16) float hbuf[2][HD];
    __shared__ int xs[T_LEN];

    const int tid = threadIdx.x;
    const int n   = blockIdx.x >> 3;     // batch row
    const int r   = blockIdx.x & 7;      // cluster rank
    const int f   = tid >> 2;            // 0..63
    const int sub = tid & 3;             // 0..3
    const int jg  = r * 64 + f;          // global feature

    // preload Wh row slice into registers in chunk order (q*4+sub)
    ull w[64];
    {
        const float4* wr = (const float4*)(Wh + (size_t)jg * HD);
#pragma unroll
        for (int q = 0; q < 32; q++) {
            float4 v = __ldg(&wr[q * 4 + sub]);
            w[2 * q + 0] = pack2(v.x, v.y);
            w[2 * q + 1] = pack2(v.z, v.w);
        }
    }
    const float bias = (sub == 0) ? __ldg(&bh[jg]) : 0.0f;

    // stage token row, zero h0
    for (int i = tid; i < T_LEN; i += 256) xs[i] = x[n * T_LEN + i];
    if (tid < 128) ((float4*)hbuf[0])[tid] = make_float4(0.f, 0.f, 0.f, 0.f);
    __syncthreads();
    CLUSTER_SYNC();  // DSMEM readiness

    float eb = 0.0f;
    if (sub == 0) eb = __ldg(&E[(size_t)xs[0] * HD + jg]) + bias;

    const unsigned hb0 = smem_u32(&hbuf[0][jg]);
    const unsigned hb1 = smem_u32(&hbuf[1][jg]);

    for (int t = 0; t < T_LEN; t++) {
        const int par = t & 1, nxt = par ^ 1;

        // prefetch next step's embedding (hidden behind the dot chain)
        float ebn = 0.0f;
        if (sub == 0) {
            int tn = xs[(t + 1 < T_LEN) ? t + 1 : t];
            ebn = __ldg(&E[(size_t)tn * HD + jg]) + bias;
        }

        const ulonglong2* hp = (const ulonglong2*)hbuf[par];
        ull a0 = 0, a1 = 0, a2 = 0, a3 = 0;
#pragma unroll
        for (int q = 0; q < 32; q += 2) {
            ulonglong2 h0 = hp[q * 4 + sub];
            ulonglong2 h1 = hp[(q + 1) * 4 + sub];
            fma2(a0, w[2 * q + 0], h0.x);
            fma2(a1, w[2 * q + 1], h0.y);
            fma2(a2, w[2 * q + 2], h1.x);
            fma2(a3, w[2 * q + 3], h1.y);
        }
        float2 f0 = unpack2(a0), f1 = unpack2(a1), f2 = unpack2(a2), f3 = unpack2(a3);
        float s = (f0.x + f0.y) + (f1.x + f1.y) + (f2.x + f2.y) + (f3.x + f3.y);
        s += __shfl_down_sync(0xffffffffu, s, 2);
        s += __shfl_down_sync(0xffffffffu, s, 1);

        if (sub == 0) {
            float hv = tanhf(s + eb);
            __stcg(&g_Hall[((size_t)(t * 8 + n)) * HD + jg], hv);
            if (t == T_LEN - 1) g_hfin[n * HD + jg] = hv;
            const unsigned laddr = nxt ? hb1 : hb0;
#pragma unroll
            for (int p = 0; p < 8; p++) st_cluster_f32(laddr, (unsigned)p, hv);
        }
        CLUSTER_SYNC();  // orders DSMEM stores; releases step t+1
        eb = ebn;
    }
}

// ---------------- phase 2: z = H_all @ Wo^T + bo  (writes raw logits to out) ----------------
__global__ __launch_bounds__(256, 2) void gemm_kernel(const float* __restrict__ Wo,
                                                      const float* __restrict__ bo,
                                                      float* __restrict__ out) {
    __shared__ ull Asp[16 * 130];   // [kk2][m] padded
    __shared__ ull Bsp[16 * 66];    // [kk2][v] padded
    const int tid = threadIdx.x;
    const int bn = blockIdx.x, bm = blockIdx.y;
    const int m0 = tid & 15;             // rows m0 + 16*i
    const int n0 = (tid >> 4) << 2;      // cols n0..n0+3

    ull acc[8][4];
#pragma unroll
    for (int i = 0; i < 8; i++)
#pragma unroll
        for (int j = 0; j < 4; j++) acc[i][j] = 0;

    const float* Ab = g_Hall + (size_t)bm * 128 * HD;

    for (int k0 = 0; k0 < HD; k0 += 32) {
#pragma unroll
        for (int j = 0; j < 4; j++) {                 // A tile: 128x32
            int lin = tid + j * 256;
            int m = lin >> 3, kq = lin & 7;
            float4 v = *(const float4*)(Ab + (size_t)m * HD + k0 + (kq << 2));
            Asp[(kq * 2 + 0) * 130 + m] = pack2(v.x, v.y);
            Asp[(kq * 2 + 1) * 130 + m] = pack2(v.z, v.w);
        }
#pragma unroll
        for (int j = 0; j < 2; j++) {                 // B tile: 64x32 (guarded at V edge)
            int lin = tid + j * 256;
            int vl = lin >> 3, kq = lin & 7;
            int col = bn * 64 + vl;
            float4 v = make_float4(0.f, 0.f, 0.f, 0.f);
            if (col < VO) v = *(const float4*)(Wo + (size_t)col * HD + k0 + (kq << 2));
            Bsp[(kq * 2 + 0) * 66 + vl] = pack2(v.x, v.y);
            Bsp[(kq * 2 + 1) * 66 + vl] = pack2(v.z, v.w);
        }
        __syncthreads();
#pragma unroll
        for (int kk2 = 0; kk2 < 16; kk2++) {
            ull a[8], b[4];
#pragma unroll
            for (int i = 0; i < 8; i++) a[i] = Asp[kk2 * 130 + m0 + (i << 4)];
#pragma unroll
            for (int j = 0; j < 4; j++) b[j] = Bsp[kk2 * 66 + n0 + j];
#pragma unroll
            for (int i = 0; i < 8; i++)
#pragma unroll
                for (int j = 0; j < 4; j++) fma2(acc[i][j], a[i], b[j]);
        }
        __syncthreads();
    }

    float bov[4];
#pragma unroll
    for (int j = 0; j < 4; j++) {
        int col = bn * 64 + n0 + j;
        bov[j] = (col < VO) ? __ldg(&bo[col]) : 0.0f;
    }
#pragma unroll
    for (int i = 0; i < 8; i++) {
        int rr = bm * 128 + m0 + (i << 4);
        int tt = rr >> 3, n = rr & 7;
        float* orow = out + (size_t)(n * T_LEN + tt) * VO;
#pragma unroll
        for (int j = 0; j < 4; j++) {
            int col = bn * 64 + n0 + j;
            if (col < VO) {
                float2 fv = unpack2(acc[i][j]);
                orow[col] = fv.x + fv.y + bov[j];
            }
        }
    }
}

// ---------------- phase 3: in-place row softmax (row held in registers) ----------------
__global__ __launch_bounds__(256) void softmax_kernel(float* __restrict__ out) {
    const int row = blockIdx.x;
    float* p = out + (size_t)row * VO;
    const int tid = threadIdx.x;
    __shared__ float red[8];

    float v[20];
    float mx = -3.0e38f;
#pragma unroll
    for (int s = 0; s < 20; s++) {
        int i = tid + (s << 8);
        v[s] = (i < VO) ? p[i] : -3.0e38f;
        mx = fmaxf(mx, v[s]);
    }
#pragma unroll
    for (int o = 16; o; o >>= 1) mx = fmaxf(mx, __shfl_xor_sync(0xffffffffu, mx, o));
    if ((tid & 31) == 0) red[tid >> 5] = mx;
    __syncthreads();
    if (tid == 0) {
        float m = red[0];
#pragma unroll
        for (int w = 1; w < 8; w++) m = fmaxf(m, red[w]);
        red[0] = m;
    }
    __syncthreads();
    mx = red[0];

    float sum = 0.0f;
#pragma unroll
    for (int s = 0; s < 20; s++) {
        float e = __expf(v[s] - mx);
        v[s] = e;
        sum += e;
    }
#pragma unroll
    for (int o = 16; o; o >>= 1) sum += __shfl_xor_sync(0xffffffffu, sum, o);
    __syncthreads();
    if ((tid & 31) == 0) red[tid >> 5] = sum;
    __syncthreads();
    if (tid == 0) {
        float s2 = 0.0f;
#pragma unroll
        for (int w = 0; w < 8; w++) s2 += red[w];
        red[0] = s2;
    }
    __syncthreads();
    float rr = 1.0f / red[0];
#pragma unroll
    for (int s = 0; s < 20; s++) {
        int i = tid + (s << 8);
        if (i < VO) p[i] = v[s] * rr;
    }
}

// ---------------- h_final tail ----------------
__global__ void copyh_kernel(float* __restrict__ out) {
    int i = blockIdx.x * 256 + threadIdx.x;
    if (i < NB * HD) out[(size_t)Y_ELEMS + i] = g_hfin[i];
}

extern "C" void kernel_launch(void* const* d_in, const int* in_sizes, int n_in,
                              void* d_out, int out_size) {
    const int*   x  = (const int*)d_in[0];
    const float* E  = (const float*)d_in[1];
    const float* Wh = (const float*)d_in[2];
    const float* bh = (const float*)d_in[3];
    const float* Wo = (const float*)d_in[4];
    const float* bo = (const float*)d_in[5];
    float* out = (float*)d_out;

    rnn_kernel<<<64, 256>>>(x, E, Wh, bh);
    dim3 g((VO + 63) / 64, NT / 128);
    gemm_kernel<<<g, 256>>>(Wo, bo, out);
    softmax_kernel<<<NT, 256>>>(out);
    if (out_size >= Y_ELEMS + NB * HD) copyh_kernel<<<16, 256>>>(out);
}

// round 4
// speedup vs baseline: 1.8600x; 1.1659x over previous
#include <cuda_runtime.h>
#include <cuda_bf16.h>
#include <cstdint>

#define T_LEN 2048
#define NB 8
#define HD 512
#define VO 5000
#define VOP 5120                        // padded vocab rows
#define KE 1536                         // extended K: [hi | lo | hi] x [hi | hi | lo]
#define NT (T_LEN * NB)                 // 16384
#define Y_ELEMS (NB * T_LEN * VO)       // 81,920,000

typedef unsigned long long ull;

// ---------------- device scratch (static: no allocation allowed) ----------------
__device__ __align__(16) __nv_bfloat16 g_A[(size_t)NT * KE];    // 50.3 MB
__device__ __align__(16) __nv_bfloat16 g_B[(size_t)VOP * KE];   // 15.7 MB
__device__ float g_hfin[NB * HD];

// ---------------- helpers ----------------
__device__ __forceinline__ ull pack2(float x, float y) {
    ull r; asm("mov.b64 %0, {%1, %2};" : "=l"(r) : "f"(x), "f"(y)); return r;
}
__device__ __forceinline__ float2 unpack2(ull a) {
    float2 f; asm("mov.b64 {%0, %1}, %2;" : "=f"(f.x), "=f"(f.y) : "l"(a)); return f;
}
__device__ __forceinline__ void fma2(ull& d, ull a, ull b) {
    asm("fma.rn.f32x2 %0, %1, %2, %0;" : "+l"(d) : "l"(a), "l"(b));
}
__device__ __forceinline__ unsigned smem_u32(const void* p) {
    unsigned a;
    asm("{ .reg .u64 t; cvta.to.shared.u64 t, %1; cvt.u32.u64 %0, t; }" : "=r"(a) : "l"(p));
    return a;
}
__device__ __forceinline__ void st_cluster_f32(unsigned local_addr, unsigned rank, float v) {
    unsigned ra;
    asm("mapa.shared::cluster.u32 %0, %1, %2;" : "=r"(ra) : "r"(local_addr), "r"(rank));
    asm volatile("st.shared::cluster.f32 [%0], %1;" :: "r"(ra), "f"(v) : "memory");
}

// ---------------- phase 1: recurrence via CGA (8 CTAs per batch row) ----------------
__global__ __cluster_dims__(8, 1, 1) __launch_bounds__(256)
void rnn_kernel(const int* __restrict__ x,
                const float* __restrict__ E,
                const float* __restrict__ Wh,
                const float* __restrict__ bh) {
    __shared__ __align__(16) float hbuf[2][HD];
    __shared__ int xs[T_LEN];

    const int tid = threadIdx.x;
    const int n   = blockIdx.x >> 3;     // batch row
    const int r   = blockIdx.x & 7;      // cluster rank
    const int f   = tid >> 2;            // 0..63
    const int sub = tid & 3;             // 0..3
    const int jg  = r * 64 + f;          // global feature

    ull w[64];
    {
        const float4* wr = (const float4*)(Wh + (size_t)jg * HD);
#pragma unroll
        for (int q = 0; q < 32; q++) {
            float4 v = __ldg(&wr[q * 4 + sub]);
            w[2 * q + 0] = pack2(v.x, v.y);
            w[2 * q + 1] = pack2(v.z, v.w);
        }
    }
    const float bias = (sub == 0) ? __ldg(&bh[jg]) : 0.0f;

    for (int i = tid; i < T_LEN; i += 256) xs[i] = x[n * T_LEN + i];
    if (tid < 128) ((float4*)hbuf[0])[tid] = make_float4(0.f, 0.f, 0.f, 0.f);
    __syncthreads();
    asm volatile("barrier.cluster.arrive.aligned;" ::: "memory");
    asm volatile("barrier.cluster.wait.aligned;"   ::: "memory");

    float eb = 0.0f;
    if (sub == 0) eb = __ldg(&E[(size_t)xs[0] * HD + jg]) + bias;

    const unsigned hb0 = smem_u32(&hbuf[0][jg]);
    const unsigned hb1 = smem_u32(&hbuf[1][jg]);

    for (int t = 0; t < T_LEN; t++) {
        const int par = t & 1;

        const ulonglong2* hp = (const ulonglong2*)hbuf[par];
        ull a0 = 0, a1 = 0, a2 = 0, a3 = 0;
#pragma unroll
        for (int q = 0; q < 32; q += 2) {
            ulonglong2 h0 = hp[q * 4 + sub];
            ulonglong2 h1 = hp[(q + 1) * 4 + sub];
            fma2(a0, w[2 * q + 0], h0.x);
            fma2(a1, w[2 * q + 1], h0.y);
            fma2(a2, w[2 * q + 2], h1.x);
            fma2(a3, w[2 * q + 3], h1.y);
        }
        float2 f0 = unpack2(a0), f1 = unpack2(a1), f2 = unpack2(a2), f3 = unpack2(a3);
        float s = (f0.x + f0.y) + (f1.x + f1.y) + (f2.x + f2.y) + (f3.x + f3.y);
        s += __shfl_down_sync(0xffffffffu, s, 2);
        s += __shfl_down_sync(0xffffffffu, s, 1);

        if (sub == 0) {
            float hv = tanhf(s + eb);
            __nv_bfloat16 hi = __float2bfloat16(hv);
            __nv_bfloat16 lo = __float2bfloat16(hv - __bfloat162float(hi));
            size_t base = (size_t)(t * 8 + n) * KE + jg;
            g_A[base]        = hi;
            g_A[base + 512]  = lo;
            g_A[base + 1024] = hi;
            if (t == T_LEN - 1) g_hfin[n * HD + jg] = hv;
            const unsigned laddr = (par ^ 1) ? hb1 : hb0;
#pragma unroll
            for (int p = 0; p < 8; p++) st_cluster_f32(laddr, (unsigned)p, hv);
        }
        asm volatile("barrier.cluster.arrive.aligned;" ::: "memory");
        float ebn = 0.0f;
        if (sub == 0 && t + 1 < T_LEN)
            ebn = __ldg(&E[(size_t)xs[t + 1] * HD + jg]) + bias;   // hidden behind barrier wait
        asm volatile("barrier.cluster.wait.aligned;" ::: "memory");
        eb = ebn;
    }
}

// ---------------- B' builder: Wo fp32 -> [hi, hi, lo] bf16, zero-padded rows ----------------
__global__ __launch_bounds__(256) void convB_kernel(const float* __restrict__ Wo) {
    int idx = blockIdx.x * 256 + threadIdx.x;
    if (idx >= VOP * HD) return;
    int row = idx >> 9, k = idx & 511;
    float v = (row < VO) ? __ldg(&Wo[row * HD + k]) : 0.0f;
    __nv_bfloat16 hi = __float2bfloat16(v);
    __nv_bfloat16 lo = __float2bfloat16(v - __bfloat162float(hi));
    size_t b = (size_t)row * KE;
    g_B[b + k]        = hi;
    g_B[b + 512 + k]  = hi;
    g_B[b + 1024 + k] = lo;
}

// ---------------- phase 2: mma.sync bf16 GEMM  D[16384,5120] = A' @ B'^T + bo ----------------
// CTA tile 128x128, 8 warps (2m x 4n, warp tile 64x32), K-chunk 32, 3-stage cp.async.
// smem row pad: 40 bf16 (80 B) -> ldmatrix conflict-free (20-bank row stride).
#define KCH 32
#define NCHUNK (KE / KCH)        // 48
#define ROWB 80                  // padded row bytes
#define TILEB (128 * ROWB)       // 10240 per operand
#define STAGEB (2 * TILEB)       // 20480
#define GSMEM (3 * STAGEB)       // 61440

__device__ __forceinline__ void cpa16(uint32_t dst, const void* src) {
    asm volatile("cp.async.cg.shared.global [%0], [%1], 16;" :: "r"(dst), "l"(src));
}
__device__ __forceinline__ void ldm_x4(uint32_t* r, uint32_t addr) {
    asm volatile("ldmatrix.sync.aligned.m8n8.x4.shared.b16 {%0,%1,%2,%3}, [%4];"
                 : "=r"(r[0]), "=r"(r[1]), "=r"(r[2]), "=r"(r[3]) : "r"(addr));
}
__device__ __forceinline__ void mma_bf16(float* d, const uint32_t* a, const uint32_t* b) {
    asm volatile(
        "mma.sync.aligned.m16n8k16.row.col.f32.bf16.bf16.f32 "
        "{%0,%1,%2,%3}, {%4,%5,%6,%7}, {%8,%9}, {%0,%1,%2,%3};"
        : "+f"(d[0]), "+f"(d[1]), "+f"(d[2]), "+f"(d[3])
        : "r"(a[0]), "r"(a[1]), "r"(a[2]), "r"(a[3]), "r"(b[0]), "r"(b[1]));
}

__global__ __launch_bounds__(256, 2) void gemm_kernel(const float* __restrict__ bo,
                                                      float* __restrict__ out) {
    extern __shared__ char dsm[];
    const uint32_t sb = smem_u32(dsm);
    const int tid = threadIdx.x;
    const int lane = tid & 31, wid = tid >> 5;
    const int wm = wid >> 2, wn = wid & 3;       // 2 x 4
    const int bn = blockIdx.x, bm = blockIdx.y;

    const __nv_bfloat16* Ag = g_A + (size_t)bm * 128 * KE;
    const __nv_bfloat16* Bg = g_B + (size_t)bn * 128 * KE;

    // stage loader: 512 A tasks + 512 B tasks, 4 per thread
    auto load_stage = [&](int stage, int kc) {
        const uint32_t sA = sb + stage * STAGEB;
        const uint32_t sB = sA + TILEB;
#pragma unroll
        for (int j = 0; j < 2; j++) {
            int tt = tid + j * 256;
            int row = tt >> 2, c = tt & 3;
            cpa16(sA + row * ROWB + c * 16, Ag + (size_t)row * KE + kc * KCH + c * 8);
        }
#pragma unroll
        for (int j = 0; j < 2; j++) {
            int tt = tid + j * 256;
            int row = tt >> 2, c = tt & 3;
            cpa16(sB + row * ROWB + c * 16, Bg + (size_t)row * KE + kc * KCH + c * 8);
        }
        asm volatile("cp.async.commit_group;");
    };

    float acc[4][4][4];
#pragma unroll
    for (int i = 0; i < 4; i++)
#pragma unroll
        for (int j = 0; j < 4; j++)
#pragma unroll
            for (int k = 0; k < 4; k++) acc[i][j][k] = 0.0f;

    load_stage(0, 0);
    load_stage(1, 1);

    // precomputed ldmatrix lane addressing
    const int a_row = (lane & 15);
    const int a_kb  = (lane >> 4) * 16;           // byte offset of k-half
    const int b_row = (lane & 7) + ((lane >> 4) * 8);
    const int b_kb  = ((lane >> 3) & 1) * 16;

    for (int c = 0; c < NCHUNK; c++) {
        if (c < NCHUNK - 1) asm volatile("cp.async.wait_group 1;");
        else                asm volatile("cp.async.wait_group 0;");
        __syncthreads();
        if (c + 2 < NCHUNK) load_stage((c + 2) % 3, c + 2);

        const uint32_t sA = sb + (c % 3) * STAGEB;
        const uint32_t sB = sA + TILEB;
#pragma unroll
        for (int ks = 0; ks < 2; ks++) {
            uint32_t a[4][4], b[2][4];
#pragma unroll
            for (int mf = 0; mf < 4; mf++)
                ldm_x4(a[mf], sA + (wm * 64 + mf * 16 + a_row) * ROWB + ks * 32 + a_kb);
#pragma unroll
            for (int g = 0; g < 2; g++)
                ldm_x4(b[g], sB + (wn * 32 + g * 16 + b_row) * ROWB + ks * 32 + b_kb);
#pragma unroll
            for (int mf = 0; mf < 4; mf++)
#pragma unroll
                for (int nf = 0; nf < 4; nf++)
                    mma_bf16(acc[mf][nf], a[mf], &b[nf >> 1][(nf & 1) * 2]);
        }
        __syncthreads();
    }

    // epilogue: direct reg -> gmem with bias; out row = (m&7)*T_LEN + (m>>3)
#pragma unroll
    for (int nf = 0; nf < 4; nf++) {
        const int col = bn * 128 + wn * 32 + nf * 8 + (lane & 3) * 2;
        if (col >= VO) continue;
        const float bx = __ldg(&bo[col]);
        const float by = __ldg(&bo[col + 1]);
#pragma unroll
        for (int mf = 0; mf < 4; mf++) {
            const int ml = wm * 64 + mf * 16 + (lane >> 2);
#pragma unroll
            for (int h = 0; h < 2; h++) {
                const int m = bm * 128 + ml + h * 8;
                const int orow = (m & 7) * T_LEN + (m >> 3);
                float2 v = make_float2(acc[mf][nf][2 * h] + bx, acc[mf][nf][2 * h + 1] + by);
                *(float2*)&out[(size_t)orow * VO + col] = v;
            }
        }
    }
}

// ---------------- phase 3: in-place row softmax ----------------
__global__ __launch_bounds__(256) void softmax_kernel(float* __restrict__ out) {
    const int row = blockIdx.x;
    float* p = out + (size_t)row * VO;
    const int tid = threadIdx.x;
    __shared__ float red[8];

    float v[20];
    float mx = -3.0e38f;
#pragma unroll
    for (int s = 0; s < 20; s++) {
        int i = tid + (s << 8);
        v[s] = (i < VO) ? p[i] : -3.0e38f;
        mx = fmaxf(mx, v[s]);
    }
#pragma unroll
    for (int o = 16; o; o >>= 1) mx = fmaxf(mx, __shfl_xor_sync(0xffffffffu, mx, o));
    if ((tid & 31) == 0) red[tid >> 5] = mx;
    __syncthreads();
    if (tid == 0) {
        float m = red[0];
#pragma unroll
        for (int w = 1; w < 8; w++) m = fmaxf(m, red[w]);
        red[0] = m;
    }
    __syncthreads();
    mx = red[0];

    float sum = 0.0f;
#pragma unroll
    for (int s = 0; s < 20; s++) {
        float e = __expf(v[s] - mx);
        v[s] = e;
        sum += e;
    }
#pragma unroll
    for (int o = 16; o; o >>= 1) sum += __shfl_xor_sync(0xffffffffu, sum, o);
    __syncthreads();
    if ((tid & 31) == 0) red[tid >> 5] = sum;
    __syncthreads();
    if (tid == 0) {
        float s2 = 0.0f;
#pragma unroll
        for (int w = 0; w < 8; w++) s2 += red[w];
        red[0] = s2;
    }
    __syncthreads();
    float rr = 1.0f / red[0];
#pragma unroll
    for (int s = 0; s < 20; s++) {
        int i = tid + (s << 8);
        if (i < VO) p[i] = v[s] * rr;
    }
}

// ---------------- h_final tail ----------------
__global__ void copyh_kernel(float* __restrict__ out) {
    int i = blockIdx.x * 256 + threadIdx.x;
    if (i < NB * HD) out[(size_t)Y_ELEMS + i] = g_hfin[i];
}

extern "C" void kernel_launch(void* const* d_in, const int* in_sizes, int n_in,
                              void* d_out, int out_size) {
    const int*   x  = (const int*)d_in[0];
    const float* E  = (const float*)d_in[1];
    const float* Wh = (const float*)d_in[2];
    const float* bh = (const float*)d_in[3];
    const float* Wo = (const float*)d_in[4];
    const float* bo = (const float*)d_in[5];
    float* out = (float*)d_out;

    cudaFuncSetAttribute(gemm_kernel, cudaFuncAttributeMaxDynamicSharedMemorySize, GSMEM);

    convB_kernel<<<(VOP * HD + 255) / 256, 256>>>(Wo);
    rnn_kernel<<<64, 256>>>(x, E, Wh, bh);
    dim3 g(VOP / 128, NT / 128);
    gemm_kernel<<<g, 256, GSMEM>>>(bo, out);
    softmax_kernel<<<NT, 256>>>(out);
    if (out_size >= Y_ELEMS + NB * HD) copyh_kernel<<<16, 256>>>(out);
}